// round 2
// baseline (speedup 1.0000x reference)
#include <cuda_runtime.h>
#include <math.h>

#define Bsz 2048
#define Nnb 64
#define Dd  512
#define Hh  8
#define HDd 64
#define Lly 3
#define FFf 2048
#define Ee  100000
#define Rr  400

// ---------------- scratch (device globals; no allocation) ----------------
__device__ float g_Pe[(size_t)Ee * Dd];        // emb_e @ W_e   (204.8 MB)
__device__ float g_Pr[Rr * Dd];                // emb_r @ W_r
__device__ float g_h[Bsz * Dd];
__device__ float g_embq[Bsz * Dd];
__device__ float g_hWh[Bsz * Dd];
__device__ float g_qh[Bsz * Dd];
__device__ float g_Ktab[Rr * Dd];
__device__ float g_x[Bsz * Dd];
__device__ float g_mid[Bsz * FFf];
__device__ float g_u[(size_t)Bsz * Hh * Dd];   // attn @ value  (33.5 MB)
__device__ float g_Wq2[Dd * Dd];
__device__ float g_Wk2[Dd * Dd];
__device__ float g_Wv2[Dd * Dd];

// ---------------- generic fp32 SGEMM: C[M,N] = A[M,K] @ B[K,N] (+bias, act) ----------------
// BM=BN=128, BK=8, 256 threads, 8x8 per thread (split 4+4 halves).
__global__ __launch_bounds__(256) void sgemm_kernel(
    const float* __restrict__ A, const float* __restrict__ B,
    const float* __restrict__ bias, float* __restrict__ C,
    int M, int N, int K, int act)
{
    __shared__ float As[8][128];
    __shared__ float Bs[8][128];
    int tid = threadIdx.x;
    int bx = blockIdx.x, by = blockIdx.y;
    int tx = tid & 15, ty = tid >> 4;

    int a_row = tid >> 1;
    int a_col = (tid & 1) << 2;
    int b_row = tid >> 5;
    int b_col = (tid & 31) << 2;

    int ga_row = by * 128 + a_row;
    int cl_row = ga_row < M ? ga_row : (M - 1);   // clamp: garbage rows never stored
    const float* Ap = A + (size_t)cl_row * K + a_col;
    const float* Bp = B + (size_t)b_row * N + bx * 128 + b_col;

    float acc[8][8];
#pragma unroll
    for (int i = 0; i < 8; i++)
#pragma unroll
        for (int j = 0; j < 8; j++) acc[i][j] = 0.f;

    for (int k0 = 0; k0 < K; k0 += 8) {
        float4 a4 = *(const float4*)Ap;
        float4 b4 = *(const float4*)Bp;
        __syncthreads();
        As[a_col + 0][a_row] = a4.x;
        As[a_col + 1][a_row] = a4.y;
        As[a_col + 2][a_row] = a4.z;
        As[a_col + 3][a_row] = a4.w;
        *(float4*)&Bs[b_row][b_col] = b4;
        __syncthreads();
#pragma unroll
        for (int k = 0; k < 8; k++) {
            float4 a0 = *(const float4*)&As[k][ty * 4];
            float4 a1 = *(const float4*)&As[k][ty * 4 + 64];
            float4 b0 = *(const float4*)&Bs[k][tx * 4];
            float4 b1 = *(const float4*)&Bs[k][tx * 4 + 64];
            float ar[8] = {a0.x, a0.y, a0.z, a0.w, a1.x, a1.y, a1.z, a1.w};
            float br[8] = {b0.x, b0.y, b0.z, b0.w, b1.x, b1.y, b1.z, b1.w};
#pragma unroll
            for (int i = 0; i < 8; i++)
#pragma unroll
                for (int j = 0; j < 8; j++) acc[i][j] += ar[i] * br[j];
        }
        Ap += 8;
        Bp += (size_t)8 * N;
    }

#pragma unroll
    for (int i = 0; i < 8; i++) {
        int row = by * 128 + ty * 4 + (i & 3) + ((i >> 2) << 6);
        if (row >= M) continue;
#pragma unroll
        for (int half = 0; half < 2; half++) {
            int col = bx * 128 + tx * 4 + (half << 6);
            float4 v = make_float4(acc[i][half * 4 + 0], acc[i][half * 4 + 1],
                                   acc[i][half * 4 + 2], acc[i][half * 4 + 3]);
            if (bias) {
                v.x += bias[col + 0]; v.y += bias[col + 1];
                v.z += bias[col + 2]; v.w += bias[col + 3];
            }
            if (act == 1) {
                v.x = fmaxf(v.x, 0.f); v.y = fmaxf(v.y, 0.f);
                v.z = fmaxf(v.z, 0.f); v.w = fmaxf(v.w, 0.f);
            }
            *(float4*)&C[(size_t)row * N + col] = v;
        }
    }
}

// ---------------- gather h / emb_q ----------------
__global__ void gather_init(const int* __restrict__ e1, const int* __restrict__ qi,
                            const float* __restrict__ emb_e, const float* __restrict__ emb_r,
                            float* __restrict__ h, float* __restrict__ eq)
{
    int b = blockIdx.x, t = threadIdx.x;  // 128 threads
    int c = t * 4;
    *(float4*)&h[(size_t)b * Dd + c]  = *(const float4*)&emb_e[(size_t)e1[b] * Dd + c];
    *(float4*)&eq[(size_t)b * Dd + c] = *(const float4*)&emb_r[(size_t)qi[b] * Dd + c];
}

// ---------------- repack [H,D,HD] -> [D, H*HD] ----------------
__global__ void repack_w(const float* __restrict__ W, float* __restrict__ W2)
{
    int idx = blockIdx.x * 256 + threadIdx.x;   // D*D = 262144
    int d = idx >> 9, c = idx & 511;
    int hx = c >> 6, e = c & 63;
    W2[idx] = W[(((size_t)hx << 9) + d) * 64 + e];
}

// ---------------- fused attention:
//   scores from K-table -> softmax -> u[b,h,:] = sum_n attn * leaky(hWh + Pr[nbr_r] + Pe[nbr_e] + msg_b)
__global__ __launch_bounds__(128) void attn_fused(
    const float* __restrict__ qh, const float* __restrict__ Ktab,
    const int* __restrict__ nbr_r, const int* __restrict__ nbr_e,
    const float* __restrict__ masks,
    const float* __restrict__ hWh, const float* __restrict__ msg_b,
    const float* __restrict__ Pr, const float* __restrict__ Pe,
    float* __restrict__ u)
{
    int b = blockIdx.x;
    int tid = threadIdx.x;
    int warp = tid >> 5, lane = tid & 31;
    __shared__ float sq[Dd];
    __shared__ float sA[Dd];       // hWh + msg_b
    __shared__ int   srow[Nnb];    // nbr_r
    __shared__ int   se[Nnb];      // nbr_e
    __shared__ float sneg[Nnb];
    __shared__ float sattn[Nnb][Hh];

    {
        int c = tid * 4;
        *(float4*)&sq[c] = *(const float4*)&qh[(size_t)b * Dd + c];
        float4 hv = *(const float4*)&hWh[(size_t)b * Dd + c];
        float4 mb = *(const float4*)&msg_b[c];
        sA[c + 0] = hv.x + mb.x; sA[c + 1] = hv.y + mb.y;
        sA[c + 2] = hv.z + mb.z; sA[c + 3] = hv.w + mb.w;
    }
    if (tid < Nnb) {
        srow[tid] = nbr_r[b * Nnb + tid];
        se[tid]   = nbr_e[b * Nnb + tid];
        sneg[tid] = 1e31f * (1.0f - masks[b * Nnb + tid]);
    }
    __syncthreads();

    // phase 1: each warp handles heads {warp, warp+4}; lane handles n and n+32
#pragma unroll
    for (int hh = 0; hh < 2; hh++) {
        int h = warp + hh * 4;
        const float* qp = sq + h * 64;
        float sc[2];
#pragma unroll
        for (int i = 0; i < 2; i++) {
            int n = lane + i * 32;
            const float* kp = Ktab + (size_t)srow[n] * Dd + h * 64;
            float s = 0.f;
#pragma unroll
            for (int e = 0; e < 64; e += 4) {
                float4 kv = *(const float4*)(kp + e);
                float4 qv = *(const float4*)(qp + e);
                s += qv.x * kv.x + qv.y * kv.y + qv.z * kv.z + qv.w * kv.w;
            }
            sc[i] = s * 0.125f - sneg[n];
        }
        float m = fmaxf(sc[0], sc[1]);
#pragma unroll
        for (int o = 16; o; o >>= 1) m = fmaxf(m, __shfl_xor_sync(0xffffffffu, m, o));
        float e0 = expf(sc[0] - m), e1 = expf(sc[1] - m);
        float s = e0 + e1;
#pragma unroll
        for (int o = 16; o; o >>= 1) s += __shfl_xor_sync(0xffffffffu, s, o);
        float inv = 1.0f / s;
        sattn[lane][h]      = e0 * inv;
        sattn[lane + 32][h] = e1 * inv;
    }
    __syncthreads();

    // phase 2: u[b,h,d0..d0+3] = sum_n attn[h][n] * leaky(sA[d] + Pr[srow[n],d] + Pe[se[n],d])
    float uacc[Hh][4];
#pragma unroll
    for (int i = 0; i < Hh; i++)
#pragma unroll
        for (int j = 0; j < 4; j++) uacc[i][j] = 0.f;

    int d0 = tid * 4;
    float4 av = *(const float4*)&sA[d0];
#pragma unroll 2
    for (int n = 0; n < Nnb; n++) {
        float4 pr = *(const float4*)&Pr[(size_t)srow[n] * Dd + d0];
        float4 pe = *(const float4*)&Pe[(size_t)se[n] * Dd + d0];
        float t0 = pr.x + pe.x + av.x;
        float t1 = pr.y + pe.y + av.y;
        float t2 = pr.z + pe.z + av.z;
        float t3 = pr.w + pe.w + av.w;
        float v0 = fmaf(0.01f, fminf(t0, 0.f), fmaxf(t0, 0.f));
        float v1 = fmaf(0.01f, fminf(t1, 0.f), fmaxf(t1, 0.f));
        float v2 = fmaf(0.01f, fminf(t2, 0.f), fmaxf(t2, 0.f));
        float v3 = fmaf(0.01f, fminf(t3, 0.f), fmaxf(t3, 0.f));
        float4 a0 = *(const float4*)&sattn[n][0];
        float4 a1 = *(const float4*)&sattn[n][4];
        float at[8] = {a0.x, a0.y, a0.z, a0.w, a1.x, a1.y, a1.z, a1.w};
#pragma unroll
        for (int hx = 0; hx < Hh; hx++) {
            uacc[hx][0] += at[hx] * v0;
            uacc[hx][1] += at[hx] * v1;
            uacc[hx][2] += at[hx] * v2;
            uacc[hx][3] += at[hx] * v3;
        }
    }
#pragma unroll
    for (int hx = 0; hx < Hh; hx++) {
        *(float4*)&u[((size_t)b * Hh + hx) * Dd + d0] =
            make_float4(uacc[hx][0], uacc[hx][1], uacc[hx][2], uacc[hx][3]);
    }
}

// ---------------- per-head projection: x[b, h*64+e] = u[b,h,:] @ Wv2[:, h*64+e] + bv ----------------
__global__ __launch_bounds__(256) void proj_u(
    const float* __restrict__ u, const float* __restrict__ Wv2,
    const float* __restrict__ bv2, float* __restrict__ x)
{
    int h = blockIdx.y;     // 0..7
    int bt = blockIdx.x;    // 0..31 (64 b's each)
    int tid = threadIdx.x;  // 256
    __shared__ float As[64][36];
    __shared__ float Bs[32][68];
    int tx = tid & 15, ty = tid >> 4;
    float acc[4][4];
#pragma unroll
    for (int i = 0; i < 4; i++)
#pragma unroll
        for (int j = 0; j < 4; j++) acc[i][j] = 0.f;

    for (int k0 = 0; k0 < Dd; k0 += 32) {
        __syncthreads();
#pragma unroll
        for (int r = 0; r < 2; r++) {
            int rr = r * 32 + (tid >> 3);
            int cc = (tid & 7) * 4;
            int bb = bt * 64 + rr;
            *(float4*)&As[rr][cc] =
                *(const float4*)&u[((size_t)bb * Hh + h) * Dd + k0 + cc];
        }
#pragma unroll
        for (int r = 0; r < 2; r++) {
            int rr = r * 16 + (tid >> 4);
            int cc = (tid & 15) * 4;
            *(float4*)&Bs[rr][cc] =
                *(const float4*)&Wv2[(size_t)(k0 + rr) * Dd + h * 64 + cc];
        }
        __syncthreads();
#pragma unroll
        for (int k = 0; k < 32; k++) {
            float ar[4];
#pragma unroll
            for (int i = 0; i < 4; i++) ar[i] = As[ty * 4 + i][k];
            float4 br = *(const float4*)&Bs[k][tx * 4];
#pragma unroll
            for (int i = 0; i < 4; i++) {
                acc[i][0] += ar[i] * br.x;
                acc[i][1] += ar[i] * br.y;
                acc[i][2] += ar[i] * br.z;
                acc[i][3] += ar[i] * br.w;
            }
        }
    }
    float4 bias = *(const float4*)&bv2[h * 64 + tx * 4];
#pragma unroll
    for (int i = 0; i < 4; i++) {
        int bb = bt * 64 + ty * 4 + i;
        float4 v = make_float4(acc[i][0] + bias.x, acc[i][1] + bias.y,
                               acc[i][2] + bias.z, acc[i][3] + bias.w);
        *(float4*)&x[(size_t)bb * Dd + h * 64 + tx * 4] = v;
    }
}

// ---------------- residual add + LayerNorm (in place on h) ----------------
__global__ __launch_bounds__(128) void add_ln(
    float* __restrict__ h, const float* __restrict__ x,
    const float* __restrict__ g, const float* __restrict__ bt)
{
    int row = blockIdx.x, tid = threadIdx.x;   // 128 threads, 4 elems each
    int warp = tid >> 5, lane = tid & 31;
    int c = tid * 4;
    float4 hv = *(const float4*)&h[(size_t)row * Dd + c];
    float4 xv = *(const float4*)&x[(size_t)row * Dd + c];
    float y0 = hv.x + xv.x, y1 = hv.y + xv.y, y2 = hv.z + xv.z, y3 = hv.w + xv.w;
    float s = y0 + y1 + y2 + y3;
    float s2 = y0 * y0 + y1 * y1 + y2 * y2 + y3 * y3;
#pragma unroll
    for (int o = 16; o; o >>= 1) {
        s  += __shfl_xor_sync(0xffffffffu, s, o);
        s2 += __shfl_xor_sync(0xffffffffu, s2, o);
    }
    __shared__ float rs[4], rs2[4];
    if (lane == 0) { rs[warp] = s; rs2[warp] = s2; }
    __syncthreads();
    s  = rs[0] + rs[1] + rs[2] + rs[3];
    s2 = rs2[0] + rs2[1] + rs2[2] + rs2[3];
    float mean = s * (1.0f / Dd);
    float var = s2 * (1.0f / Dd) - mean * mean;
    float rstd = rsqrtf(var + 1e-5f);
    float4 gv = *(const float4*)&g[c];
    float4 bv = *(const float4*)&bt[c];
    float4 o = make_float4((y0 - mean) * rstd * gv.x + bv.x,
                           (y1 - mean) * rstd * gv.y + bv.y,
                           (y2 - mean) * rstd * gv.z + bv.z,
                           (y3 - mean) * rstd * gv.w + bv.w);
    *(float4*)&h[(size_t)row * Dd + c] = o;
}

// ---------------- final output copy: out = [h ; emb_q] ----------------
__global__ void final_copy(const float* __restrict__ h, const float* __restrict__ eq,
                           float* __restrict__ out)
{
    size_t i = ((size_t)blockIdx.x * 128 + threadIdx.x) * 4;
    *(float4*)&out[i] = *(const float4*)&h[i];
    *(float4*)&out[(size_t)Bsz * Dd + i] = *(const float4*)&eq[i];
}

// ---------------- launch ----------------
extern "C" void kernel_launch(void* const* d_in, const int* in_sizes, int n_in,
                              void* d_out, int out_size)
{
    (void)in_sizes; (void)n_in; (void)out_size;
    const int*   e1    = (const int*)d_in[0];
    const int*   qi    = (const int*)d_in[1];
    const int*   nbr_r = (const int*)d_in[2];
    const int*   nbr_e = (const int*)d_in[3];
    const float* masks = (const float*)d_in[4];
    const float* emb_e = (const float*)d_in[5];
    const float* emb_r = (const float*)d_in[6];
    const float* msg_W = (const float*)d_in[7];
    const float* msg_b = (const float*)d_in[8];
    const float* Wq    = (const float*)d_in[9];
    const float* bq    = (const float*)d_in[10];
    const float* Wk    = (const float*)d_in[11];
    const float* bk    = (const float*)d_in[12];
    const float* Wv    = (const float*)d_in[13];
    const float* bv    = (const float*)d_in[14];
    const float* fW1   = (const float*)d_in[15];
    const float* fb1   = (const float*)d_in[16];
    const float* fW2   = (const float*)d_in[17];
    const float* fb2   = (const float*)d_in[18];
    const float* l1g   = (const float*)d_in[19];
    const float* l1b   = (const float*)d_in[20];
    const float* l2g   = (const float*)d_in[21];
    const float* l2b   = (const float*)d_in[22];
    float* out = (float*)d_out;

    float *Pe, *Pr, *h, *eq, *hWh, *qh, *Kt, *xb, *mid, *u, *Wq2, *Wk2, *Wv2;
    cudaGetSymbolAddress((void**)&Pe,  g_Pe);
    cudaGetSymbolAddress((void**)&Pr,  g_Pr);
    cudaGetSymbolAddress((void**)&h,   g_h);
    cudaGetSymbolAddress((void**)&eq,  g_embq);
    cudaGetSymbolAddress((void**)&hWh, g_hWh);
    cudaGetSymbolAddress((void**)&qh,  g_qh);
    cudaGetSymbolAddress((void**)&Kt,  g_Ktab);
    cudaGetSymbolAddress((void**)&xb,  g_x);
    cudaGetSymbolAddress((void**)&mid, g_mid);
    cudaGetSymbolAddress((void**)&u,   g_u);
    cudaGetSymbolAddress((void**)&Wq2, g_Wq2);
    cudaGetSymbolAddress((void**)&Wk2, g_Wk2);
    cudaGetSymbolAddress((void**)&Wv2, g_Wv2);

    gather_init<<<Bsz, 128>>>(e1, qi, emb_e, emb_r, h, eq);

    // Pe = emb_e @ W_e (rows 2D..3D of msg_W), Pr = emb_r @ W_r (rows D..2D)
    sgemm_kernel<<<dim3(4, (Ee + 127) / 128), 256>>>(emb_e, msg_W + 1024 * 512, nullptr, Pe, Ee, Dd, Dd, 0);
    sgemm_kernel<<<dim3(4, 4), 256>>>(emb_r, msg_W + 512 * 512, nullptr, Pr, Rr, Dd, Dd, 0);

    for (int l = 0; l < Lly; l++) {
        size_t woff = (size_t)l * Hh * Dd * HDd;
        repack_w<<<1024, 256>>>(Wq + woff, Wq2);
        repack_w<<<1024, 256>>>(Wk + woff, Wk2);
        repack_w<<<1024, 256>>>(Wv + woff, Wv2);

        sgemm_kernel<<<dim3(4, 16), 256>>>(eq, Wq2, bq + l * 512, qh, Bsz, Dd, Dd, 0);
        sgemm_kernel<<<dim3(4, 4), 256>>>(emb_r, Wk2, bk + l * 512, Kt, Rr, Dd, Dd, 0);
        sgemm_kernel<<<dim3(4, 16), 256>>>(h, msg_W, nullptr, hWh, Bsz, Dd, Dd, 0); // W_h = rows 0..D

        attn_fused<<<Bsz, 128>>>(qh, Kt, nbr_r, nbr_e, masks, hWh, msg_b, Pr, Pe, u);
        proj_u<<<dim3(32, 8), 256>>>(u, Wv2, bv + l * 512, xb);
        add_ln<<<Bsz, 128>>>(h, xb, l1g + l * 512, l1b + l * 512);

        sgemm_kernel<<<dim3(16, 16), 256>>>(h, fW1 + (size_t)l * Dd * FFf, fb1 + l * FFf, mid, Bsz, FFf, Dd, 1);
        sgemm_kernel<<<dim3(4, 16), 256>>>(mid, fW2 + (size_t)l * FFf * Dd, fb2 + l * 512, xb, Bsz, Dd, FFf, 0);
        add_ln<<<Bsz, 128>>>(h, xb, l2g + l * 512, l2b + l * 512);
    }

    final_copy<<<2048, 128>>>(h, eq, out);
}

// round 4
// speedup vs baseline: 2.0233x; 2.0233x over previous
#include <cuda_runtime.h>
#include <math.h>
#include <stdint.h>

#define Bsz 2048
#define Nnb 64
#define Dd  512
#define Hh  8
#define HDd 64
#define Lly 3
#define FFf 2048
#define Ee  100000
#define Rr  400

// ---------------- scratch (device globals; no allocation) ----------------
__device__ float g_Pe[(size_t)Ee * Dd];        // emb_e @ W_e   (204.8 MB)
__device__ float g_Pr[Rr * Dd];                // emb_r @ W_r
__device__ float g_h[Bsz * Dd];
__device__ float g_embq[Bsz * Dd];
__device__ float g_hWh[Bsz * Dd];
__device__ float g_qh[Bsz * Dd];
__device__ float g_Ktab[Rr * Dd];
__device__ float g_x[Bsz * Dd];
__device__ float g_mid[Bsz * FFf];
__device__ float g_u[(size_t)Bsz * Hh * Dd];   // attn @ value  (33.5 MB)

// ---------------- tf32 helpers ----------------
__device__ __forceinline__ uint32_t f2tf(float x) {
    uint32_t r;
    asm("cvt.rna.tf32.f32 %0, %1;" : "=r"(r) : "f"(x));
    return r;
}

__device__ __forceinline__ void mma_tf32(float* c, const uint4& a, const uint2& b) {
    asm volatile(
        "mma.sync.aligned.m16n8k8.row.col.f32.tf32.tf32.f32 "
        "{%0,%1,%2,%3},{%4,%5,%6,%7},{%8,%9},{%0,%1,%2,%3};\n"
        : "+f"(c[0]), "+f"(c[1]), "+f"(c[2]), "+f"(c[3])
        : "r"(a.x), "r"(a.y), "r"(a.z), "r"(a.w), "r"(b.x), "r"(b.y));
}

// ---------------- tf32 tensor-core GEMM: C[M,N] = A[M,K] @ B[K,N] (+bias, act) ----------------
// BM=128, BN=128, BK=32; 256 threads = 8 warps (2 x 4), warp tile 64x32.
// Fragments pre-packed into smem in mma layout with XOR swizzle (conflict-free).
// bmode: 0 = B row-major [K][N]; 1 = B is [H=8][K][64] per-head blocks (N must be 512).
__global__ __launch_bounds__(256) void tgemm(
    const float* __restrict__ A, const float* __restrict__ B,
    const float* __restrict__ bias, float* __restrict__ C,
    int M, int N, int K, int act, int bmode)
{
    // As: [ks=4][mtile=8][lane=32][areg=4]  (16KB)
    // Bs: [ks=4][ntile=16][lane=32][breg=2] (16KB)
    __shared__ uint32_t As[4 * 8 * 32 * 4];
    __shared__ uint32_t Bs[4 * 16 * 32 * 2];

    int tid = threadIdx.x;
    int warp = tid >> 5, lane = tid & 31;
    int wm = warp & 1, wn = warp >> 1;
    int bx = blockIdx.x, by = blockIdx.y;

    float acc[4][4][4];
#pragma unroll
    for (int mt = 0; mt < 4; mt++)
#pragma unroll
        for (int nt = 0; nt < 4; nt++)
#pragma unroll
            for (int i = 0; i < 4; i++) acc[mt][nt][i] = 0.f;

    // static per-thread load coords
    int a_r[4], a_c4[4], b_k[4], b_c4[4];
#pragma unroll
    for (int i = 0; i < 4; i++) {
        int fA = i * 256 + tid;
        a_r[i] = fA >> 3;          // 0..127
        a_c4[i] = fA & 7;          // float4 index within 32 cols
        int fB = i * 256 + tid;
        b_k[i] = fB >> 5;          // 0..31
        b_c4[i] = fB & 31;         // float4 index within 128 cols
    }

    for (int k0 = 0; k0 < K; k0 += 32) {
        float4 av[4], bv[4];
#pragma unroll
        for (int i = 0; i < 4; i++) {
            int rg = by * 128 + a_r[i];
            int rc = rg < M ? rg : (M - 1);
            av[i] = *(const float4*)&A[(size_t)rc * K + k0 + a_c4[i] * 4];
        }
#pragma unroll
        for (int i = 0; i < 4; i++) {
            int krow = k0 + b_k[i];
            int ncol = bx * 128 + b_c4[i] * 4;
            const float* bp;
            if (bmode == 0) bp = &B[(size_t)krow * N + ncol];
            else {
                int hh = ncol >> 6, e = ncol & 63;
                bp = &B[((size_t)hh * K + krow) * 64 + e];
            }
            bv[i] = *(const float4*)bp;
        }
        __syncthreads();
        // scatter A into fragment layout
#pragma unroll
        for (int i = 0; i < 4; i++) {
            int r = a_r[i];
            int ks = a_c4[i] >> 1;
            int half = a_c4[i] & 1;          // c base 0 or 4
            int mtile = r >> 4;
            int r15 = r & 15;
            int reg = half * 2 + (r15 >> 3);
            int lbase = (r15 & 7) * 4;
            uint32_t baseidx = (((ks << 3) + mtile) << 7) + reg;
            float vv[4] = {av[i].x, av[i].y, av[i].z, av[i].w};
#pragma unroll
            for (int j = 0; j < 4; j++) {
                int ln = (lbase + j) ^ ks;
                As[baseidx + (ln << 2)] = f2tf(vv[j]);
            }
        }
        // scatter B into fragment layout
#pragma unroll
        for (int i = 0; i < 4; i++) {
            int kl = b_k[i] & 7;
            int ks = b_k[i] >> 3;
            int reg = kl >> 2;
            int km = kl & 3;
            float vv[4] = {bv[i].x, bv[i].y, bv[i].z, bv[i].w};
#pragma unroll
            for (int j = 0; j < 4; j++) {
                int ng = b_c4[i] * 4 + j;    // 0..127
                int ntile = ng >> 3;
                int nl = ng & 7;
                int ln = (nl * 4 + km) ^ ntile;
                Bs[(((ks << 4) + ntile) << 6) + (ln << 1) + reg] = f2tf(vv[j]);
            }
        }
        __syncthreads();
        // compute
#pragma unroll
        for (int ks = 0; ks < 4; ks++) {
            uint4 af[4];
            uint2 bf[4];
#pragma unroll
            for (int mt = 0; mt < 4; mt++)
                af[mt] = *(const uint4*)&As[(((ks << 3) + (wm << 2) + mt) << 7) + ((lane ^ ks) << 2)];
#pragma unroll
            for (int nt = 0; nt < 4; nt++) {
                int ntile = (wn << 2) + nt;
                bf[nt] = *(const uint2*)&Bs[(((ks << 4) + ntile) << 6) + ((lane ^ ntile) << 1)];
            }
#pragma unroll
            for (int mt = 0; mt < 4; mt++)
#pragma unroll
                for (int nt = 0; nt < 4; nt++)
                    mma_tf32(acc[mt][nt], af[mt], bf[nt]);
        }
    }

    // epilogue
    int r_in = lane >> 2, c_in = (lane & 3) * 2;
#pragma unroll
    for (int mt = 0; mt < 4; mt++) {
        int row0 = by * 128 + wm * 64 + mt * 16 + r_in;
#pragma unroll
        for (int half = 0; half < 2; half++) {
            int row = row0 + half * 8;
            if (row >= M) continue;
#pragma unroll
            for (int nt = 0; nt < 4; nt++) {
                int col = bx * 128 + wn * 32 + nt * 8 + c_in;
                float v0 = acc[mt][nt][half * 2 + 0];
                float v1 = acc[mt][nt][half * 2 + 1];
                if (bias) { v0 += bias[col]; v1 += bias[col + 1]; }
                if (act == 1) { v0 = fmaxf(v0, 0.f); v1 = fmaxf(v1, 0.f); }
                *(float2*)&C[(size_t)row * N + col] = make_float2(v0, v1);
            }
        }
    }
}

// ---------------- gather h / emb_q ----------------
__global__ void gather_init(const int* __restrict__ e1, const int* __restrict__ qi,
                            const float* __restrict__ emb_e, const float* __restrict__ emb_r,
                            float* __restrict__ h, float* __restrict__ eq)
{
    int b = blockIdx.x, t = threadIdx.x;  // 128 threads
    int c = t * 4;
    *(float4*)&h[(size_t)b * Dd + c]  = *(const float4*)&emb_e[(size_t)e1[b] * Dd + c];
    *(float4*)&eq[(size_t)b * Dd + c] = *(const float4*)&emb_r[(size_t)qi[b] * Dd + c];
}

// ---------------- fused attention:
//   scores from K-table -> softmax -> u[b,h,:] = sum_n attn * leaky(hWh + Pr[nbr_r] + Pe[nbr_e] + msg_b)
__global__ __launch_bounds__(128) void attn_fused(
    const float* __restrict__ qh, const float* __restrict__ Ktab,
    const int* __restrict__ nbr_r, const int* __restrict__ nbr_e,
    const float* __restrict__ masks,
    const float* __restrict__ hWh, const float* __restrict__ msg_b,
    const float* __restrict__ Pr, const float* __restrict__ Pe,
    float* __restrict__ u)
{
    int b = blockIdx.x;
    int tid = threadIdx.x;
    int warp = tid >> 5, lane = tid & 31;
    __shared__ float sq[Dd];
    __shared__ float sA[Dd];       // hWh + msg_b
    __shared__ int   srow[Nnb];    // nbr_r
    __shared__ int   se[Nnb];      // nbr_e
    __shared__ float sneg[Nnb];
    __shared__ float sattn[Nnb][Hh];

    {
        int c = tid * 4;
        *(float4*)&sq[c] = *(const float4*)&qh[(size_t)b * Dd + c];
        float4 hv = *(const float4*)&hWh[(size_t)b * Dd + c];
        float4 mb = *(const float4*)&msg_b[c];
        sA[c + 0] = hv.x + mb.x; sA[c + 1] = hv.y + mb.y;
        sA[c + 2] = hv.z + mb.z; sA[c + 3] = hv.w + mb.w;
    }
    if (tid < Nnb) {
        srow[tid] = nbr_r[b * Nnb + tid];
        se[tid]   = nbr_e[b * Nnb + tid];
        sneg[tid] = 1e31f * (1.0f - masks[b * Nnb + tid]);
    }
    __syncthreads();

    // phase 1: each warp handles heads {warp, warp+4}; lane handles n and n+32
#pragma unroll
    for (int hh = 0; hh < 2; hh++) {
        int h = warp + hh * 4;
        const float* qp = sq + h * 64;
        float sc[2];
#pragma unroll
        for (int i = 0; i < 2; i++) {
            int n = lane + i * 32;
            const float* kp = Ktab + (size_t)srow[n] * Dd + h * 64;
            float s = 0.f;
#pragma unroll
            for (int e = 0; e < 64; e += 4) {
                float4 kv = *(const float4*)(kp + e);
                float4 qv = *(const float4*)(qp + e);
                s += qv.x * kv.x + qv.y * kv.y + qv.z * kv.z + qv.w * kv.w;
            }
            sc[i] = s * 0.125f - sneg[n];
        }
        float m = fmaxf(sc[0], sc[1]);
#pragma unroll
        for (int o = 16; o; o >>= 1) m = fmaxf(m, __shfl_xor_sync(0xffffffffu, m, o));
        float e0 = expf(sc[0] - m), e1 = expf(sc[1] - m);
        float s = e0 + e1;
#pragma unroll
        for (int o = 16; o; o >>= 1) s += __shfl_xor_sync(0xffffffffu, s, o);
        float inv = 1.0f / s;
        sattn[lane][h]      = e0 * inv;
        sattn[lane + 32][h] = e1 * inv;
    }
    __syncthreads();

    // phase 2: u[b,h,d0..d0+3] = sum_n attn[h][n] * leaky(sA[d] + Pr[srow[n],d] + Pe[se[n],d])
    float uacc[Hh][4];
#pragma unroll
    for (int i = 0; i < Hh; i++)
#pragma unroll
        for (int j = 0; j < 4; j++) uacc[i][j] = 0.f;

    int d0 = tid * 4;
    float4 av = *(const float4*)&sA[d0];
#pragma unroll 2
    for (int n = 0; n < Nnb; n++) {
        float4 pr = *(const float4*)&Pr[(size_t)srow[n] * Dd + d0];
        float4 pe = *(const float4*)&Pe[(size_t)se[n] * Dd + d0];
        float t0 = pr.x + pe.x + av.x;
        float t1 = pr.y + pe.y + av.y;
        float t2 = pr.z + pe.z + av.z;
        float t3 = pr.w + pe.w + av.w;
        float v0 = fmaf(0.01f, fminf(t0, 0.f), fmaxf(t0, 0.f));
        float v1 = fmaf(0.01f, fminf(t1, 0.f), fmaxf(t1, 0.f));
        float v2 = fmaf(0.01f, fminf(t2, 0.f), fmaxf(t2, 0.f));
        float v3 = fmaf(0.01f, fminf(t3, 0.f), fmaxf(t3, 0.f));
        float4 a0 = *(const float4*)&sattn[n][0];
        float4 a1 = *(const float4*)&sattn[n][4];
        float at[8] = {a0.x, a0.y, a0.z, a0.w, a1.x, a1.y, a1.z, a1.w};
#pragma unroll
        for (int hx = 0; hx < Hh; hx++) {
            uacc[hx][0] += at[hx] * v0;
            uacc[hx][1] += at[hx] * v1;
            uacc[hx][2] += at[hx] * v2;
            uacc[hx][3] += at[hx] * v3;
        }
    }
#pragma unroll
    for (int hx = 0; hx < Hh; hx++) {
        *(float4*)&u[((size_t)b * Hh + hx) * Dd + d0] =
            make_float4(uacc[hx][0], uacc[hx][1], uacc[hx][2], uacc[hx][3]);
    }
}

// ---------------- per-head projection: x[b, h*64+e] = u[b,h,:] @ Wv[h,:,e] + bv ----------------
// Wv layout: [H][D][HD] (per layer slice passed in)
__global__ __launch_bounds__(256) void proj_u(
    const float* __restrict__ u, const float* __restrict__ Wv,
    const float* __restrict__ bv2, float* __restrict__ x)
{
    int h = blockIdx.y;     // 0..7
    int bt = blockIdx.x;    // 0..31 (64 b's each)
    int tid = threadIdx.x;  // 256
    __shared__ float As[64][36];
    __shared__ float Bs[32][68];
    int tx = tid & 15, ty = tid >> 4;
    float acc[4][4];
#pragma unroll
    for (int i = 0; i < 4; i++)
#pragma unroll
        for (int j = 0; j < 4; j++) acc[i][j] = 0.f;

    for (int k0 = 0; k0 < Dd; k0 += 32) {
        __syncthreads();
#pragma unroll
        for (int r = 0; r < 2; r++) {
            int rr = r * 32 + (tid >> 3);
            int cc = (tid & 7) * 4;
            int bb = bt * 64 + rr;
            *(float4*)&As[rr][cc] =
                *(const float4*)&u[((size_t)bb * Hh + h) * Dd + k0 + cc];
        }
#pragma unroll
        for (int r = 0; r < 2; r++) {
            int rr = r * 16 + (tid >> 4);
            int cc = (tid & 15) * 4;
            *(float4*)&Bs[rr][cc] =
                *(const float4*)&Wv[((size_t)h * Dd + k0 + rr) * HDd + cc];
        }
        __syncthreads();
#pragma unroll
        for (int k = 0; k < 32; k++) {
            float ar[4];
#pragma unroll
            for (int i = 0; i < 4; i++) ar[i] = As[ty * 4 + i][k];
            float4 br = *(const float4*)&Bs[k][tx * 4];
#pragma unroll
            for (int i = 0; i < 4; i++) {
                acc[i][0] += ar[i] * br.x;
                acc[i][1] += ar[i] * br.y;
                acc[i][2] += ar[i] * br.z;
                acc[i][3] += ar[i] * br.w;
            }
        }
    }
    float4 bias = *(const float4*)&bv2[h * 64 + tx * 4];
#pragma unroll
    for (int i = 0; i < 4; i++) {
        int bb = bt * 64 + ty * 4 + i;
        float4 v = make_float4(acc[i][0] + bias.x, acc[i][1] + bias.y,
                               acc[i][2] + bias.z, acc[i][3] + bias.w);
        *(float4*)&x[(size_t)bb * Dd + h * 64 + tx * 4] = v;
    }
}

// ---------------- residual add + LayerNorm (in place on h) ----------------
__global__ __launch_bounds__(128) void add_ln(
    float* __restrict__ h, const float* __restrict__ x,
    const float* __restrict__ g, const float* __restrict__ bt)
{
    int row = blockIdx.x, tid = threadIdx.x;   // 128 threads, 4 elems each
    int warp = tid >> 5, lane = tid & 31;
    int c = tid * 4;
    float4 hv = *(const float4*)&h[(size_t)row * Dd + c];
    float4 xv = *(const float4*)&x[(size_t)row * Dd + c];
    float y0 = hv.x + xv.x, y1 = hv.y + xv.y, y2 = hv.z + xv.z, y3 = hv.w + xv.w;
    float s = y0 + y1 + y2 + y3;
    float s2 = y0 * y0 + y1 * y1 + y2 * y2 + y3 * y3;
#pragma unroll
    for (int o = 16; o; o >>= 1) {
        s  += __shfl_xor_sync(0xffffffffu, s, o);
        s2 += __shfl_xor_sync(0xffffffffu, s2, o);
    }
    __shared__ float rs[4], rs2[4];
    if (lane == 0) { rs[warp] = s; rs2[warp] = s2; }
    __syncthreads();
    s  = rs[0] + rs[1] + rs[2] + rs[3];
    s2 = rs2[0] + rs2[1] + rs2[2] + rs2[3];
    float mean = s * (1.0f / Dd);
    float var = s2 * (1.0f / Dd) - mean * mean;
    float rstd = rsqrtf(var + 1e-5f);
    float4 gv = *(const float4*)&g[c];
    float4 bv = *(const float4*)&bt[c];
    float4 o = make_float4((y0 - mean) * rstd * gv.x + bv.x,
                           (y1 - mean) * rstd * gv.y + bv.y,
                           (y2 - mean) * rstd * gv.z + bv.z,
                           (y3 - mean) * rstd * gv.w + bv.w);
    *(float4*)&h[(size_t)row * Dd + c] = o;
}

// ---------------- final output copy: out = [h ; emb_q] ----------------
__global__ void final_copy(const float* __restrict__ h, const float* __restrict__ eq,
                           float* __restrict__ out)
{
    size_t i = ((size_t)blockIdx.x * 128 + threadIdx.x) * 4;
    *(float4*)&out[i] = *(const float4*)&h[i];
    *(float4*)&out[(size_t)Bsz * Dd + i] = *(const float4*)&eq[i];
}

// ---------------- launch ----------------
extern "C" void kernel_launch(void* const* d_in, const int* in_sizes, int n_in,
                              void* d_out, int out_size)
{
    (void)in_sizes; (void)n_in; (void)out_size;
    const int*   e1    = (const int*)d_in[0];
    const int*   qi    = (const int*)d_in[1];
    const int*   nbr_r = (const int*)d_in[2];
    const int*   nbr_e = (const int*)d_in[3];
    const float* masks = (const float*)d_in[4];
    const float* emb_e = (const float*)d_in[5];
    const float* emb_r = (const float*)d_in[6];
    const float* msg_W = (const float*)d_in[7];
    const float* msg_b = (const float*)d_in[8];
    const float* Wq    = (const float*)d_in[9];
    const float* bq    = (const float*)d_in[10];
    const float* Wk    = (const float*)d_in[11];
    const float* bk    = (const float*)d_in[12];
    const float* Wv    = (const float*)d_in[13];
    const float* bv    = (const float*)d_in[14];
    const float* fW1   = (const float*)d_in[15];
    const float* fb1   = (const float*)d_in[16];
    const float* fW2   = (const float*)d_in[17];
    const float* fb2   = (const float*)d_in[18];
    const float* l1g   = (const float*)d_in[19];
    const float* l1b   = (const float*)d_in[20];
    const float* l2g   = (const float*)d_in[21];
    const float* l2b   = (const float*)d_in[22];
    float* out = (float*)d_out;

    float *Pe, *Pr, *h, *eq, *hWh, *qh, *Kt, *xb, *mid, *u;
    cudaGetSymbolAddress((void**)&Pe,  g_Pe);
    cudaGetSymbolAddress((void**)&Pr,  g_Pr);
    cudaGetSymbolAddress((void**)&h,   g_h);
    cudaGetSymbolAddress((void**)&eq,  g_embq);
    cudaGetSymbolAddress((void**)&hWh, g_hWh);
    cudaGetSymbolAddress((void**)&qh,  g_qh);
    cudaGetSymbolAddress((void**)&Kt,  g_Ktab);
    cudaGetSymbolAddress((void**)&xb,  g_x);
    cudaGetSymbolAddress((void**)&mid, g_mid);
    cudaGetSymbolAddress((void**)&u,   g_u);

    gather_init<<<Bsz, 128>>>(e1, qi, emb_e, emb_r, h, eq);

    // Pe = emb_e @ W_e (rows 2D..3D of msg_W), Pr = emb_r @ W_r (rows D..2D)
    tgemm<<<dim3(4, (Ee + 127) / 128), 256>>>(emb_e, msg_W + 1024 * 512, nullptr, Pe, Ee, Dd, Dd, 0, 0);
    tgemm<<<dim3(4, 4), 256>>>(emb_r, msg_W + 512 * 512, nullptr, Pr, Rr, Dd, Dd, 0, 0);

    for (int l = 0; l < Lly; l++) {
        size_t woff = (size_t)l * Hh * Dd * HDd;

        tgemm<<<dim3(4, 16), 256>>>(eq, Wq + woff, bq + l * 512, qh, Bsz, Dd, Dd, 0, 1);
        tgemm<<<dim3(4, 4), 256>>>(emb_r, Wk + woff, bk + l * 512, Kt, Rr, Dd, Dd, 0, 1);
        tgemm<<<dim3(4, 16), 256>>>(h, msg_W, nullptr, hWh, Bsz, Dd, Dd, 0, 0); // W_h = rows 0..D

        attn_fused<<<Bsz, 128>>>(qh, Kt, nbr_r, nbr_e, masks, hWh, msg_b, Pr, Pe, u);
        proj_u<<<dim3(32, 8), 256>>>(u, Wv + woff, bv + l * 512, xb);
        add_ln<<<Bsz, 128>>>(h, xb, l1g + l * 512, l1b + l * 512);

        tgemm<<<dim3(16, 16), 256>>>(h, fW1 + (size_t)l * Dd * FFf, fb1 + l * FFf, mid, Bsz, FFf, Dd, 1, 0);
        tgemm<<<dim3(4, 16), 256>>>(mid, fW2 + (size_t)l * FFf * Dd, fb2 + l * 512, xb, Bsz, Dd, FFf, 0, 0);
        add_ln<<<Bsz, 128>>>(h, xb, l2g + l * 512, l2b + l * 512);
    }

    final_copy<<<2048, 128>>>(h, eq, out);
}